// round 6
// baseline (speedup 1.0000x reference)
#include <cuda_runtime.h>
#include <cuda_bf16.h>

#define N_NODES   4000000
#define N_GRAPHS  4096
#define D_FEAT    8
#define N_CLASSES 10
#define N_F4      (N_NODES * 2)          // 8,000,000 float4s
#define WCH       512                     // float4s per chunk (256 rows)
#define N_CHUNKS  (N_F4 / WCH)            // 15625
#define B_BLOCKS  1776                    // 148 SMs * 12 blocks
#define B_THREADS 128
#define B_WARPS   (B_BLOCKS * (B_THREADS / 32))   // 7104
#define FULL 0xFFFFFFFFu

__device__ int   g_seg_start[N_GRAPHS + 1];
__device__ float g_sums[N_GRAPHS * D_FEAT];

// batch_ids may be int64 OR int32 (JAX under default x64=False silently makes
// them int32). Values < 4096, so for int64 data every high word is 0: viewing
// as int32, element N_NODES-1 is an int64 high word (==0) or the max id (>0).
__device__ __forceinline__ int id_at(const int* __restrict__ ids32, bool is64, int i) {
    return is64 ? ids32[2 * i] : ids32[i];
}

// ---------------- Kernel A: boundaries (warp-cooperative 32-ary) + zero ----
__global__ __launch_bounds__(256) void bounds_kernel(const int* __restrict__ ids32) {
    const int tid  = blockIdx.x * blockDim.x + threadIdx.x;
    // zero g_sums
    if (tid < N_GRAPHS * D_FEAT) g_sums[tid] = 0.0f;

    const int warp_g = tid >> 5;          // one warp per boundary value
    const int lane   = threadIdx.x & 31;
    if (warp_g > N_GRAPHS) return;
    const int v = warp_g;                 // lower_bound target (0..4096)

    const bool is64 = (ids32[N_NODES - 1] == 0);

    int lo, hi;
    if (v >= N_GRAPHS) { lo = hi = N_NODES; }
    else {
        const long long approx = ((long long)v * N_NODES) >> 12;
        lo = (int)(approx - 32768); if (lo < 0) lo = 0;
        hi = (int)(approx + 32768); if (hi > N_NODES) hi = N_NODES;
        const bool ok_lo = (lo == 0)       || (id_at(ids32, is64, lo - 1) < v);
        const bool ok_hi = (hi == N_NODES) || (id_at(ids32, is64, hi) >= v);
        if (!(ok_lo && ok_hi)) { lo = 0; hi = N_NODES; }
    }
    // 32-ary cooperative lower_bound
    while (hi - lo > 32) {
        const int range = hi - lo;
        const int pos = lo + (int)(((long long)range * (lane + 1)) >> 5);  // in (lo, hi]
        const bool less = id_at(ids32, is64, pos - 1) < v;
        const unsigned ball = __ballot_sync(FULL, less);
        const int cnt = __popc(ball);                    // monotone prefix length
        const int nlo = lo + (int)(((long long)range * cnt) >> 5);
        const int nhi = (cnt == 32) ? hi
                      : lo + (int)(((long long)range * (cnt + 1)) >> 5);
        lo = nlo; hi = nhi;
    }
    {   // final resolve among <=32 candidates
        const int pos = lo + lane;
        const bool less = (pos < hi) ? (id_at(ids32, is64, pos) < v) : false;
        const unsigned ball = __ballot_sync(FULL, less);
        lo = lo + __popc(ball);
    }
    if (lane == 0) g_seg_start[v] = lo;
}

// ---------------- Kernel B: flat stream + per-run atomics --------------------
__global__ __launch_bounds__(B_THREADS, 10) void stream_kernel(
    const float4* __restrict__ x4)
{
    const int lane = threadIdx.x & 31;
    const int wid  = (blockIdx.x * B_THREADS + threadIdx.x) >> 5;

    for (int chunk = wid; chunk < N_CHUNKS; chunk += B_WARPS) {
        const int f0 = chunk * WCH;
        const int f1 = f0 + WCH;
        const int row0 = f0 >> 1;

        // locate first segment via L2-resident seg_start (approx + short walk)
        int s = (int)(((long long)row0 << 12) / N_NODES);
        if (s > N_GRAPHS - 1) s = N_GRAPHS - 1;
        while (__ldg(&g_seg_start[s + 1]) <= row0) s++;
        while (__ldg(&g_seg_start[s])     >  row0) s--;

        int c0 = f0;
        while (c0 < f1) {
            const int seg_end2 = __ldg(&g_seg_start[s + 1]) * 2;
            const int e = (seg_end2 < f1) ? seg_end2 : f1;

            float4 a0 = make_float4(0.f,0.f,0.f,0.f);
            float4 a1 = make_float4(0.f,0.f,0.f,0.f);
            float4 a2 = make_float4(0.f,0.f,0.f,0.f);
            float4 a3 = make_float4(0.f,0.f,0.f,0.f);

            int j = c0 + lane;
            while (j + 224 < e) {       // unroll 8
                float4 v0 = __ldg(&x4[j      ]);
                float4 v1 = __ldg(&x4[j +  32]);
                float4 v2 = __ldg(&x4[j +  64]);
                float4 v3 = __ldg(&x4[j +  96]);
                float4 v4 = __ldg(&x4[j + 128]);
                float4 v5 = __ldg(&x4[j + 160]);
                float4 v6 = __ldg(&x4[j + 192]);
                float4 v7 = __ldg(&x4[j + 224]);
                a0.x += v0.x; a0.y += v0.y; a0.z += v0.z; a0.w += v0.w;
                a1.x += v1.x; a1.y += v1.y; a1.z += v1.z; a1.w += v1.w;
                a2.x += v2.x; a2.y += v2.y; a2.z += v2.z; a2.w += v2.w;
                a3.x += v3.x; a3.y += v3.y; a3.z += v3.z; a3.w += v3.w;
                a0.x += v4.x; a0.y += v4.y; a0.z += v4.z; a0.w += v4.w;
                a1.x += v5.x; a1.y += v5.y; a1.z += v5.z; a1.w += v5.w;
                a2.x += v6.x; a2.y += v6.y; a2.z += v6.z; a2.w += v6.w;
                a3.x += v7.x; a3.y += v7.y; a3.z += v7.z; a3.w += v7.w;
                j += 256;
            }
            for (; j < e; j += 32) {
                float4 vv = __ldg(&x4[j]);
                a0.x += vv.x; a0.y += vv.y; a0.z += vv.z; a0.w += vv.w;
            }
            a0.x += a1.x + a2.x + a3.x;
            a0.y += a1.y + a2.y + a3.y;
            a0.z += a1.z + a2.z + a3.z;
            a0.w += a1.w + a2.w + a3.w;

            // Parity butterfly (run start c0 is even, so lane parity == f4 parity):
            // lane 0 -> cols 0-3, lane 1 -> cols 4-7.
            #pragma unroll
            for (int m = 16; m >= 2; m >>= 1) {
                a0.x += __shfl_xor_sync(FULL, a0.x, m);
                a0.y += __shfl_xor_sync(FULL, a0.y, m);
                a0.z += __shfl_xor_sync(FULL, a0.z, m);
                a0.w += __shfl_xor_sync(FULL, a0.w, m);
            }
            // redistribute: lane d (0..7) gets column d
            const int src = lane >> 2;                 // 0 for cols 0-3, 1 for 4-7
            const float vx = __shfl_sync(FULL, a0.x, src);
            const float vy = __shfl_sync(FULL, a0.y, src);
            const float vz = __shfl_sync(FULL, a0.z, src);
            const float vw = __shfl_sync(FULL, a0.w, src);
            if (lane < D_FEAT) {
                const float val = (lane & 2) ? ((lane & 1) ? vw : vz)
                                             : ((lane & 1) ? vy : vx);
                atomicAdd(&g_sums[s * D_FEAT + lane], val);
            }
            c0 = e; s++;
        }
    }
}

// ---------------- Kernel C: finalize mean + tiny GEMM ------------------------
__global__ __launch_bounds__(256) void finalize_kernel(
    const float* __restrict__ W, const float* __restrict__ b,
    float* __restrict__ out)
{
    const int g = blockIdx.x * blockDim.x + threadIdx.x;
    if (g >= N_GRAPHS) return;
    const int cnt = g_seg_start[g + 1] - g_seg_start[g];
    const float inv = (cnt > 0) ? (1.0f / (float)cnt) : 0.0f;
    float p[D_FEAT];
    #pragma unroll
    for (int k = 0; k < D_FEAT; k++) p[k] = g_sums[g * D_FEAT + k] * inv;
    #pragma unroll
    for (int c = 0; c < N_CLASSES; c++) {
        float r = __ldg(&b[c]);
        #pragma unroll
        for (int k = 0; k < D_FEAT; k++) r += p[k] * __ldg(&W[c * D_FEAT + k]);
        out[g * N_CLASSES + c] = r;
    }
}

extern "C" void kernel_launch(void* const* d_in, const int* in_sizes, int n_in,
                              void* d_out, int out_size) {
    // Bind inputs by element count (robust to metadata ordering):
    //   x: 32,000,000 f32 | batch_ids: 4,000,000 | W: 80 | b: 10
    const float* x   = nullptr;
    const void*  ids = nullptr;
    const float* W   = nullptr;
    const float* b   = nullptr;
    for (int i = 0; i < n_in; i++) {
        switch (in_sizes[i]) {
            case N_NODES * D_FEAT:   x   = (const float*)d_in[i]; break;
            case N_NODES:            ids = d_in[i];               break;
            case N_CLASSES * D_FEAT: W   = (const float*)d_in[i]; break;
            case N_CLASSES:          b   = (const float*)d_in[i]; break;
            default: break; // input_ids / attention_mask: unused
        }
    }
    float* out = (float*)d_out;

    bounds_kernel<<<513, 256>>>((const int*)ids);          // 4104 warps >= 4097
    stream_kernel<<<B_BLOCKS, B_THREADS>>>((const float4*)x);
    finalize_kernel<<<(N_GRAPHS + 255) / 256, 256>>>(W, b, out);
}

// round 7
// speedup vs baseline: 1.3333x; 1.3333x over previous
#include <cuda_runtime.h>
#include <cuda_bf16.h>

#define N_NODES   4000000
#define N_GRAPHS  4096
#define D_FEAT    8
#define N_CLASSES 10
#define WARPS_PER_BLOCK 4
#define N_BLOCKS (N_GRAPHS / WARPS_PER_BLOCK)
#define FULL 0xFFFFFFFFu

// batch_ids may be int64 OR int32 (JAX under default x64=False silently makes
// them int32). Values < 4096, so for int64 data every high word is 0: viewing
// the buffer as int32, element N_NODES-1 is an int64 high word (==0) or the
// max sorted int32 id (>0).
__device__ __forceinline__ int id_at(const int* __restrict__ ids32, bool is64, int i) {
    return is64 ? ids32[2 * i] : ids32[i];
}

// Half-warp cooperative 16-ary lower_bound of v over sorted ids in [lo, hi).
__device__ __forceinline__ int kary_lower_bound(
    const int* __restrict__ ids32, bool is64, int v,
    int lo, int hi, int sub, int half_shift)
{
    const unsigned hmask = 0xFFFFu << half_shift;
    while (hi - lo > 16) {
        const int range = hi - lo;
        const int pos = lo + (int)(((long long)range * (sub + 1)) >> 4);
        const bool less = id_at(ids32, is64, pos - 1) < v;
        const unsigned ball = __ballot_sync(hmask, less);
        const int cnt = __popc((ball >> half_shift) & 0xFFFFu);
        const int nlo = lo + (int)(((long long)range * cnt) >> 4);
        const int nhi = (cnt == 16) ? hi
                      : lo + (int)(((long long)range * (cnt + 1)) >> 4);
        lo = nlo; hi = nhi;
    }
    const int pos = lo + sub;
    const bool less = (pos < hi) ? (id_at(ids32, is64, pos) < v) : false;
    const unsigned ball = __ballot_sync(hmask, less);
    return lo + __popc((ball >> half_shift) & 0xFFFFu);
}

__global__ __launch_bounds__(128) void fused_pool_gemm_kernel(
    const float4* __restrict__ x4,
    const int*    __restrict__ ids32,
    const float*  __restrict__ W,      // [10, 8]
    const float*  __restrict__ b,      // [10]
    float*        __restrict__ out)    // [4096, 10]
{
    const int warp = threadIdx.x >> 5;
    const int lane = threadIdx.x & 31;
    const int g    = blockIdx.x * WARPS_PER_BLOCK + warp;   // segment id

    // ---- Phase 0: L2 prefetch of this segment's head (16 KB at approx) ----
    // Segment start ~ Binomial: |start - g*N/B| < ~1000 rows (8 sd = 8192 is
    // ultra-safe). Prefetch rows [approx, approx+512): DRAM does useful work
    // while the dependent-load search below runs; the first ~16KB of the
    // stream then hits L2.
    {
        long long arow = ((long long)g * N_NODES) >> 12;
        if (arow > N_NODES - 512) arow = N_NODES - 512;
        const char* pbase = (const char*)x4 + arow * 32 + (long long)lane * 128;
        #pragma unroll
        for (int k = 0; k < 4; k++)
            asm volatile("prefetch.global.L2 [%0];" :: "l"(pbase + k * 4096));
    }

    // ---- Phase 1: per-warp cooperative boundary search ----
    const bool is64 = (ids32[N_NODES - 1] == 0);
    const int half_shift = lane & 16;
    const int sub = lane & 15;
    const int v = (half_shift == 0) ? g : g + 1;   // lower half: start; upper: end

    int res;
    if (v >= N_GRAPHS) {
        res = N_NODES;
    } else {
        // +-8192 window (>=8 sd); bracket-verified with full-range fallback.
        const long long approx = ((long long)v * N_NODES) >> 12;
        int lo = (int)(approx - 8192); if (lo < 0) lo = 0;
        int hi = (int)(approx + 8192); if (hi > N_NODES) hi = N_NODES;
        const bool ok_lo = (lo == 0)       || (id_at(ids32, is64, lo - 1) < v);
        const bool ok_hi = (hi == N_NODES) || (id_at(ids32, is64, hi) >= v);
        if (!(ok_lo && ok_hi)) { lo = 0; hi = N_NODES; }
        res = kary_lower_bound(ids32, is64, v, lo, hi, sub, half_shift);
    }
    __syncwarp(FULL);
    const int start = __shfl_sync(FULL, res, 0);
    const int end   = __shfl_sync(FULL, res, 16);
    const int cnt   = end - start;
    const long long base = (long long)start * 2;   // float4 units
    const int n4 = cnt * 2;

    // ---- Phase 2: float4 streaming reduction, unroll 8 ----
    float4 acc0 = make_float4(0.f,0.f,0.f,0.f);
    float4 acc1 = make_float4(0.f,0.f,0.f,0.f);
    float4 acc2 = make_float4(0.f,0.f,0.f,0.f);
    float4 acc3 = make_float4(0.f,0.f,0.f,0.f);

    int c = 0;
    while (c + 256 <= n4) {
        const long long p = base + c + lane;
        float4 v0 = __ldg(&x4[p      ]);
        float4 v1 = __ldg(&x4[p +  32]);
        float4 v2 = __ldg(&x4[p +  64]);
        float4 v3 = __ldg(&x4[p +  96]);
        float4 v4 = __ldg(&x4[p + 128]);
        float4 v5 = __ldg(&x4[p + 160]);
        float4 v6 = __ldg(&x4[p + 192]);
        float4 v7 = __ldg(&x4[p + 224]);
        acc0.x += v0.x; acc0.y += v0.y; acc0.z += v0.z; acc0.w += v0.w;
        acc1.x += v1.x; acc1.y += v1.y; acc1.z += v1.z; acc1.w += v1.w;
        acc2.x += v2.x; acc2.y += v2.y; acc2.z += v2.z; acc2.w += v2.w;
        acc3.x += v3.x; acc3.y += v3.y; acc3.z += v3.z; acc3.w += v3.w;
        acc0.x += v4.x; acc0.y += v4.y; acc0.z += v4.z; acc0.w += v4.w;
        acc1.x += v5.x; acc1.y += v5.y; acc1.z += v5.z; acc1.w += v5.w;
        acc2.x += v6.x; acc2.y += v6.y; acc2.z += v6.z; acc2.w += v6.w;
        acc3.x += v7.x; acc3.y += v7.y; acc3.z += v7.z; acc3.w += v7.w;
        c += 256;
    }
    for (int j = c + lane; j < n4; j += 32) {
        float4 vv = __ldg(&x4[base + j]);
        acc0.x += vv.x; acc0.y += vv.y; acc0.z += vv.z; acc0.w += vv.w;
    }
    acc0.x += acc1.x + acc2.x + acc3.x;
    acc0.y += acc1.y + acc2.y + acc3.y;
    acc0.z += acc1.z + acc2.z + acc3.z;
    acc0.w += acc1.w + acc2.w + acc3.w;

    // Parity-preserving butterfly: lane 0 -> cols 0-3, lane 1 -> cols 4-7.
    #pragma unroll
    for (int m = 16; m >= 2; m >>= 1) {
        acc0.x += __shfl_xor_sync(FULL, acc0.x, m);
        acc0.y += __shfl_xor_sync(FULL, acc0.y, m);
        acc0.z += __shfl_xor_sync(FULL, acc0.z, m);
        acc0.w += __shfl_xor_sync(FULL, acc0.w, m);
    }

    // ---- Phase 3: broadcast pooled vector via shuffles, fused tiny GEMM ----
    const float inv = (cnt > 0) ? (1.0f / (float)cnt) : 0.0f;
    const float p0 = __shfl_sync(FULL, acc0.x, 0) * inv;
    const float p1 = __shfl_sync(FULL, acc0.y, 0) * inv;
    const float p2 = __shfl_sync(FULL, acc0.z, 0) * inv;
    const float p3 = __shfl_sync(FULL, acc0.w, 0) * inv;
    const float p4 = __shfl_sync(FULL, acc0.x, 1) * inv;
    const float p5 = __shfl_sync(FULL, acc0.y, 1) * inv;
    const float p6 = __shfl_sync(FULL, acc0.z, 1) * inv;
    const float p7 = __shfl_sync(FULL, acc0.w, 1) * inv;

    if (lane < N_CLASSES) {
        const float* w = W + lane * D_FEAT;
        float r = __ldg(&b[lane]);
        r += p0 * __ldg(&w[0]) + p1 * __ldg(&w[1]) + p2 * __ldg(&w[2]) + p3 * __ldg(&w[3]);
        r += p4 * __ldg(&w[4]) + p5 * __ldg(&w[5]) + p6 * __ldg(&w[6]) + p7 * __ldg(&w[7]);
        out[g * N_CLASSES + lane] = r;
    }
}

extern "C" void kernel_launch(void* const* d_in, const int* in_sizes, int n_in,
                              void* d_out, int out_size) {
    // Bind inputs by element count (robust to metadata ordering):
    //   x: 32,000,000 f32 | batch_ids: 4,000,000 | W: 80 | b: 10
    const float* x   = nullptr;
    const void*  ids = nullptr;
    const float* W   = nullptr;
    const float* b   = nullptr;
    for (int i = 0; i < n_in; i++) {
        switch (in_sizes[i]) {
            case N_NODES * D_FEAT:   x   = (const float*)d_in[i]; break;
            case N_NODES:            ids = d_in[i];               break;
            case N_CLASSES * D_FEAT: W   = (const float*)d_in[i]; break;
            case N_CLASSES:          b   = (const float*)d_in[i]; break;
            default: break; // input_ids / attention_mask: unused
        }
    }
    float* out = (float*)d_out;

    fused_pool_gemm_kernel<<<N_BLOCKS, 128>>>(
        (const float4*)x, (const int*)ids, W, b, out);
}